// round 5
// baseline (speedup 1.0000x reference)
#include <cuda_runtime.h>
#include <cuda_bf16.h>
#include <cuda_fp8.h>
#include <cstdint>

#define BPAIRS 4096
#define NROWS  8192
#define DCOLS  256

#define TL 64                  // tile grid dim (8192/128)
#define NT 2080                // TL*(TL+1)/2
#define GRID 296               // persistent CTAs (2 per SM on 148 SMs)

#define SKB 272                // padded smem row stride bytes
#define TILEB (128 * SKB)      // 34816 B per operand tile
#define A_OFF 0
#define B0_OFF TILEB
#define B1_OFF (2 * TILEB)
#define RED_OFF (3 * TILEB)    // 104448
#define SMEM_TOTAL (RED_OFF + 64)

#define QSCALE 16.0f           // g_fp8 = 256 * g_true
// exp2 arg: (4*g_true - 4)*log2e = gv*C1 - C2
#define C1 (4.0f / 256.0f * 1.4426950408889634f)
#define C2 (4.0f * 1.4426950408889634f)

__device__ __align__(16) uint8_t g_X[NROWS * DCOLS];   // e4m3, scaled by 16
__device__ float g_align[BPAIRS];
__device__ float g_uni[GRID];
__device__ unsigned int g_done;

__device__ __forceinline__ uint32_t smem_u32(const void* p) {
    uint32_t a;
    asm("{ .reg .u64 t; cvta.to.shared.u64 t, %1; cvt.u32.u64 %0, t; }" : "=r"(a) : "l"(p));
    return a;
}
__device__ __forceinline__ void qmma(float d[4], const uint32_t a[4], uint32_t b0, uint32_t b1) {
    asm volatile(
        "mma.sync.aligned.m16n8k32.row.col.f32.e4m3.e4m3.f32 "
        "{%0,%1,%2,%3}, {%4,%5,%6,%7}, {%8,%9}, {%0,%1,%2,%3};\n"
        : "+f"(d[0]), "+f"(d[1]), "+f"(d[2]), "+f"(d[3])
        : "r"(a[0]), "r"(a[1]), "r"(a[2]), "r"(a[3]), "r"(b0), "r"(b1));
}
__device__ __forceinline__ void ldsm4(uint32_t r[4], uint32_t addr) {
    asm volatile("ldmatrix.sync.aligned.m8n8.x4.shared.b16 {%0,%1,%2,%3}, [%4];"
                 : "=r"(r[0]), "=r"(r[1]), "=r"(r[2]), "=r"(r[3]) : "r"(addr));
}
__device__ __forceinline__ void cpasync16(uint32_t dst, const void* src) {
    asm volatile("cp.async.cg.shared.global [%0], [%1], 16;" :: "r"(dst), "l"(src));
}
__device__ __forceinline__ float ex2(float x) {
    float r;
    asm("ex2.approx.ftz.f32 %0, %1;" : "=f"(r) : "f"(x));
    return r;
}

// normalize (fp32), per-row align partial, emit e4m3 scaled by 16
__global__ void k_norm(const float* __restrict__ A, const float* __restrict__ B) {
    int r = blockIdx.x;
    int t = threadIdx.x;           // 256 == DCOLS
    if (r == 0 && t == 0) g_done = 0u;
    float a = A[r * DCOLS + t];
    float b = B[r * DCOLS + t];
    float sa = a * a, sb = b * b;
    #pragma unroll
    for (int o = 16; o; o >>= 1) {
        sa += __shfl_xor_sync(0xffffffffu, sa, o);
        sb += __shfl_xor_sync(0xffffffffu, sb, o);
    }
    __shared__ float ssa[8], ssb[8], sdd[8];
    int wid = t >> 5, lane = t & 31;
    if (lane == 0) { ssa[wid] = sa; ssb[wid] = sb; }
    __syncthreads();
    float na = 0.f, nb = 0.f;
    #pragma unroll
    for (int i = 0; i < 8; i++) { na += ssa[i]; nb += ssb[i]; }
    na = fmaxf(sqrtf(na), 1e-12f);
    nb = fmaxf(sqrtf(nb), 1e-12f);
    float an = a / na, bn = b / nb;
    g_X[r * DCOLS + t] =
        (uint8_t)__nv_cvt_float_to_fp8(an * QSCALE, __NV_SATFINITE, __NV_E4M3);
    g_X[(BPAIRS + r) * DCOLS + t] =
        (uint8_t)__nv_cvt_float_to_fp8(bn * QSCALE, __NV_SATFINITE, __NV_E4M3);
    float d = an - bn;
    float dd = d * d;
    #pragma unroll
    for (int o = 16; o; o >>= 1) dd += __shfl_xor_sync(0xffffffffu, dd, o);
    if (lane == 0) sdd[wid] = dd;
    __syncthreads();
    if (t == 0) {
        float s = 0.f;
        #pragma unroll
        for (int i = 0; i < 8; i++) s += sdd[i];
        g_align[r] = s;
    }
}

// persistent fp8 Gram: 296 CTAs, contiguous row-major tile ranges over the
// upper triangle. A resident per row; B double-buffered + prefetched.
__global__ __launch_bounds__(256, 2) void k_gram(float* __restrict__ out) {
    extern __shared__ __align__(128) char smem[];
    uint32_t sb = smem_u32(smem);
    float* sred = (float*)(smem + RED_OFF);
    int* sflag = (int*)(smem + RED_OFF + 32);

    int tid = threadIdx.x;
    int wid = tid >> 5, lane = tid & 31;
    int wm = wid >> 1, wn = wid & 1;
    int m0 = wm * 32, n0 = wn * 64;
    int cta = blockIdx.x;

    int lo = (int)(((long long)cta * NT) / GRID);
    int hi = (int)(((long long)(cta + 1) * NT) / GRID);

    // decode lo -> (bi, bj)
    int bi = 0, rem = lo, rl = TL;
    while (rem >= rl) { rem -= rl; bi++; rl--; }
    int bj = bi + rem;

    // per-lane fragment offsets within a tile buffer
    uint32_t a_off = (uint32_t)((m0 + (lane & 15)) * SKB + ((lane >> 4) << 4));
    int bcol = (lane & 7) + ((lane >> 4) << 3);
    uint32_t b_off = (uint32_t)((n0 + bcol) * SKB + ((lane & 8) ? 16 : 0));

    // stage helpers (all 256 threads): 2048 x 16B chunks
    auto stage = [&](uint32_t dstoff, int row128) {
        const uint8_t* g = &g_X[(size_t)row128 * 128 * DCOLS];
        #pragma unroll
        for (int i = 0; i < 8; i++) {
            int idx = tid + i * 256;
            int r = idx >> 4, u = idx & 15;
            cpasync16(sb + dstoff + r * SKB + u * 16, g + (size_t)r * DCOLS + u * 16);
        }
    };

    float srun = 0.0f;
    int buf = 0;

    // prologue: A(bi) + B(bj) into buf0
    stage(A_OFF, bi);
    stage(B0_OFF, bj);
    asm volatile("cp.async.commit_group;" ::: "memory");

    for (int t = lo; t < hi; t++) {
        int nbi = bi, nbj = bj + 1;
        if (nbj >= TL) { nbi = bi + 1; nbj = nbi; }
        bool has_next = (t + 1 < hi);
        bool rowchg = (nbi != bi);

        asm volatile("cp.async.wait_group 0;" ::: "memory");
        __syncthreads();

        // prefetch next B (same row) before mainloop so it overlaps compute
        if (has_next && !rowchg) {
            stage(buf ? B0_OFF : B1_OFF, nbj);
            asm volatile("cp.async.commit_group;" ::: "memory");
        }

        uint32_t abase = sb + A_OFF + a_off;
        uint32_t bbase = sb + (buf ? B1_OFF : B0_OFF) + b_off;

        float acc[2][8][4];
        #pragma unroll
        for (int mi = 0; mi < 2; mi++)
            #pragma unroll
            for (int ni = 0; ni < 8; ni++)
                #pragma unroll
                for (int e = 0; e < 4; e++) acc[mi][ni][e] = 0.0f;

        #pragma unroll
        for (int ks = 0; ks < DCOLS / 32; ks++) {
            uint32_t a0[4], a1[4];
            ldsm4(a0, abase + ks * 32);
            ldsm4(a1, abase + 16 * SKB + ks * 32);
            #pragma unroll
            for (int nb = 0; nb < 4; nb++) {
                uint32_t bf[4];
                ldsm4(bf, bbase + nb * 16 * SKB + ks * 32);
                qmma(acc[0][2 * nb + 0], a0, bf[0], bf[1]);
                qmma(acc[0][2 * nb + 1], a0, bf[2], bf[3]);
                qmma(acc[1][2 * nb + 0], a1, bf[0], bf[1]);
                qmma(acc[1][2 * nb + 1], a1, bf[2], bf[3]);
            }
        }

        // epilogue: exp2(min(gv*C1 - C2, 0)), accumulate in-register
        float s = 0.0f;
        #pragma unroll
        for (int mi = 0; mi < 2; mi++)
            #pragma unroll
            for (int ni = 0; ni < 8; ni++)
                #pragma unroll
                for (int e = 0; e < 4; e++) {
                    float tt = fminf(acc[mi][ni][e] * C1 - C2, 0.0f);
                    s += ex2(tt);
                }
        srun += (bi == bj) ? s : 2.0f * s;

        if (has_next && rowchg) {
            __syncthreads();   // all warps done reading A before overwrite
            stage(A_OFF, nbi);
            stage(buf ? B0_OFF : B1_OFF, nbj);
            asm volatile("cp.async.commit_group;" ::: "memory");
        }
        bi = nbi; bj = nbj; buf ^= 1;
    }

    // per-CTA reduction -> g_uni[cta]
    #pragma unroll
    for (int o = 16; o; o >>= 1) srun += __shfl_xor_sync(0xffffffffu, srun, o);
    if (lane == 0) sred[wid] = srun;
    __syncthreads();
    if (tid == 0) {
        float tot = 0.f;
        #pragma unroll
        for (int i = 0; i < 8; i++) tot += sred[i];
        g_uni[cta] = tot;
        __threadfence();
        unsigned int prev = atomicAdd(&g_done, 1u);
        sflag[0] = (prev == GRID - 1) ? 1 : 0;
    }
    __syncthreads();

    // last CTA finalizes
    if (sflag[0]) {
        float sa = 0.f, su = 0.f;
        for (int i = tid; i < BPAIRS; i += 256) sa += g_align[i];
        for (int i = tid; i < GRID; i += 256) su += g_uni[i];
        float v = sa + 0.0f;
        #pragma unroll
        for (int o = 16; o; o >>= 1) {
            sa += __shfl_xor_sync(0xffffffffu, sa, o);
            su += __shfl_xor_sync(0xffffffffu, su, o);
        }
        if (lane == 0) { sred[wid] = sa; sred[wid + 8] = su; }
        __syncthreads();
        if (tid == 0) {
            float ta = 0.f, tu = 0.f;
            #pragma unroll
            for (int i = 0; i < 8; i++) { ta += sred[i]; tu += sred[i + 8]; }
            float align_loss = ta / (float)BPAIRS;
            float uniform_loss = (tu - (float)NROWS) / ((float)NROWS * (float)(NROWS - 1));
            out[0] = align_loss + uniform_loss;
        }
        (void)v;
    }
}

extern "C" void kernel_launch(void* const* d_in, const int* in_sizes, int n_in,
                              void* d_out, int out_size) {
    const float* A = (const float*)d_in[0];
    const float* B = (const float*)d_in[1];
    float* out = (float*)d_out;

    cudaFuncSetAttribute(k_gram, cudaFuncAttributeMaxDynamicSharedMemorySize, SMEM_TOTAL);

    k_norm<<<BPAIRS, 256>>>(A, B);
    k_gram<<<GRID, 256, SMEM_TOTAL>>>(out);
}